// round 9
// baseline (speedup 1.0000x reference)
#include <cuda_runtime.h>
#include <cuda_fp16.h>
#include <math.h>
#include <stdint.h>

#define Bb 8
#define Ss 4096
#define Hn 512
#define Kd 512
#define Mtot (Bb*Ss)          // 32768

#define CHUNKS2 256
#define TLEN2 (Ss/CHUNKS2)    // 16

// ------------------------- scratch (device globals) -------------------------
__device__ __align__(256) __half  g_xh[(size_t)Mtot*Kd];
__device__ __align__(256) float2  g_ab[(size_t)Mtot*Hn];
__device__ __align__(256) float2  g_loc[2][Bb*CHUNKS2*Hn];
__device__ __align__(256) float2  g_inc[2][Bb*CHUNKS2*Hn];
__device__ __align__(256) int     g_fl [2][Bb*CHUNKS2];
// 0: wz0, 1: wh0, 2: wz1, 3: wh1 (fp16)
__device__ __align__(256) __half  g_w[4][(size_t)Kd*Hn];

// ------------------------------ helpers ------------------------------------
__device__ __forceinline__ uint32_t s2u(const void* p) {
    uint32_t a;
    asm("{ .reg .u64 t; cvta.to.shared.u64 t, %1; cvt.u32.u64 %0, t; }"
        : "=r"(a) : "l"(p));
    return a;
}

__device__ __forceinline__ void cpa16(uint32_t dst, const void* src) {
    asm volatile("cp.async.cg.shared.global [%0], [%1], 16;" :: "r"(dst), "l"(src));
}

__device__ __forceinline__ void mma_f16(float* d, const uint32_t* a,
                                        uint32_t b0, uint32_t b1) {
    asm volatile(
        "mma.sync.aligned.m16n8k16.row.col.f32.f16.f16.f32 "
        "{%0,%1,%2,%3}, {%4,%5,%6,%7}, {%8,%9}, {%0,%1,%2,%3};"
        : "+f"(d[0]), "+f"(d[1]), "+f"(d[2]), "+f"(d[3])
        : "r"(a[0]), "r"(a[1]), "r"(a[2]), "r"(a[3]), "r"(b0), "r"(b1));
}

__device__ __forceinline__ void ldsm4(uint32_t* r, uint32_t addr) {
    asm volatile("ldmatrix.sync.aligned.m8n8.x4.shared.b16 {%0,%1,%2,%3}, [%4];"
        : "=r"(r[0]), "=r"(r[1]), "=r"(r[2]), "=r"(r[3]) : "r"(addr));
}

// ------------------------------- conversions -------------------------------
__global__ void clear_flags()
{
    int i = blockIdx.x * blockDim.x + threadIdx.x;
    if (i < 2 * Bb * CHUNKS2) ((int*)g_fl)[i] = 0;
}

__global__ void conv_x_kern(const float* __restrict__ src) {
    int i = blockIdx.x * blockDim.x + threadIdx.x;   // over Mtot*Kd/4
    float4 v = ((const float4*)src)[i];
    __half2 p0 = __floats2half2_rn(v.x, v.y);
    __half2 p1 = __floats2half2_rn(v.z, v.w);
    ((__half2*)g_xh)[2*i  ] = p0;
    ((__half2*)g_xh)[2*i+1] = p1;
}

__global__ void conv_w_all(const float* __restrict__ w0, const float* __restrict__ w1,
                           const float* __restrict__ w2, const float* __restrict__ w3) {
    const float* srcs[4] = {w0, w1, w2, w3};
    const int wsel = blockIdx.y;
    int i = blockIdx.x * blockDim.x + threadIdx.x;   // over Kd*Hn/4
    float4 v = ((const float4*)srcs[wsel])[i];
    __half2 p0 = __floats2half2_rn(v.x, v.y);
    __half2 p1 = __floats2half2_rn(v.z, v.w);
    ((__half2*)g_w[wsel])[2*i  ] = p0;
    ((__half2*)g_w[wsel])[2*i+1] = p1;
}

// --------------------------- mma.sync dual GEMM -----------------------------
// CTA tile 128M x 64N. Warp-specialized: warps 0-3 compute Z, warps 4-7 compute H.
// Each warp: 32M x 64N, 64 accumulator regs. 4-stage cp.async pipeline, 2 CTAs/SM.
// smem per stage: A 0 (10240B), WZ 10240 (5120B), WH 15360 (5120B), 80B row stride.
// Epilogue: both acc planes staged through smem (stride 68 floats), then fused
// activation with coalesced float4 stores.
#define KC 32
#define STAGES 4
#define STAGE_BYTES 20480
#define SMEM_BYTES (STAGES*STAGE_BYTES)
#define NCHUNK (Kd/KC)   // 16

__device__ __forceinline__ void load_stage(uint32_t sb,
    const __half* Ax, const __half* Wz, const __half* Wh,
    int rowBase, int colBase, int kOff, int tid)
{
#pragma unroll
    for (int i = 0; i < 2; i++) {
        int idx = tid + i * 256;         // 0..511
        int r   = idx >> 2;              // 0..127
        int seg = idx & 3;
        const __half* src = Ax + (size_t)(rowBase + r) * Kd + kOff + seg * 8;
        cpa16(sb + r * 80 + seg * 16, src);
    }
#pragma unroll
    for (int i = 0; i < 2; i++) {
        int idx  = tid + i * 256;        // 0..511
        int tile = idx >> 8;             // 0=Wz, 1=Wh
        int r    = (idx >> 2) & 63;
        int seg  = idx & 3;
        const __half* src = (tile ? Wh : Wz)
            + (size_t)(colBase + r) * Kd + kOff + seg * 8;
        cpa16(sb + 10240 + tile * 5120 + r * 80 + seg * 16, src);
    }
}

__global__ __launch_bounds__(256, 2)
void gemm_mma(int layer, const float* __restrict__ bz, const float* __restrict__ bh)
{
    extern __shared__ __align__(16) char sm[];
    const uint32_t sb = s2u(sm);

    const int tid  = threadIdx.x;
    const int lane = tid & 31;
    const int wid  = tid >> 5;
    const int gq   = lane >> 2;
    const int tq   = lane & 3;
    const int wm   = wid & 3;        // warp M block (32 rows)
    const int isH  = wid >> 2;       // 0 = Z matrix, 1 = H matrix

    const int rowBase = blockIdx.y * 128;
    const int colBase = blockIdx.x * 64;

    const __half* Wz = g_w[2 * layer + 0];
    const __half* Wh = g_w[2 * layer + 1];

    const uint32_t aLane = (uint32_t)((32 * wm + (lane & 15)) * 80 + ((lane >> 4) << 4));
    const uint32_t bLane = (uint32_t)((((lane >> 4) << 3) + (lane & 7)) * 80
                                      + (((lane >> 3) & 1) << 4));
    const uint32_t bOff  = 10240u + (uint32_t)isH * 5120u;

    float acc[2][8][4];
#pragma unroll
    for (int mb = 0; mb < 2; mb++)
#pragma unroll
        for (int nb = 0; nb < 8; nb++)
#pragma unroll
            for (int r = 0; r < 4; r++) acc[mb][nb][r] = 0.f;

    // prologue: chunks 0..2 into stages 0..2
#pragma unroll
    for (int s = 0; s < 3; s++) {
        load_stage(sb + s * STAGE_BYTES, g_xh, Wz, Wh, rowBase, colBase, s * KC, tid);
        asm volatile("cp.async.commit_group;" ::: "memory");
    }

    for (int c = 0; c < NCHUNK; c++) {
        if (c < NCHUNK - 2)       asm volatile("cp.async.wait_group 2;" ::: "memory");
        else if (c == NCHUNK - 2) asm volatile("cp.async.wait_group 1;" ::: "memory");
        else                      asm volatile("cp.async.wait_group 0;" ::: "memory");
        __syncthreads();

        if (c + 3 < NCHUNK) {
            load_stage(sb + ((c + 3) % STAGES) * STAGE_BYTES, g_xh, Wz, Wh,
                       rowBase, colBase, (c + 3) * KC, tid);
            asm volatile("cp.async.commit_group;" ::: "memory");
        }

        const uint32_t stg = sb + (c % STAGES) * STAGE_BYTES;
        const uint32_t aA  = stg + aLane;
        const uint32_t bB  = stg + bOff + bLane;

#pragma unroll
        for (int ks = 0; ks < 2; ks++) {
            const uint32_t kb = (uint32_t)(ks * 32);
            uint32_t Af[2][4], Bf[4][4];
#pragma unroll
            for (int mb = 0; mb < 2; mb++)
                ldsm4(Af[mb], aA + mb * (16 * 80) + kb);
#pragma unroll
            for (int p = 0; p < 4; p++)
                ldsm4(Bf[p], bB + p * (16 * 80) + kb);
#pragma unroll
            for (int p = 0; p < 4; p++)
#pragma unroll
                for (int q = 0; q < 2; q++)
#pragma unroll
                    for (int mb = 0; mb < 2; mb++)
                        mma_f16(acc[mb][2 * p + q], Af[mb], Bf[p][2*q], Bf[p][2*q+1]);
        }
    }

    // ---------------- epilogue: exchange planes via smem, activate ----------
    __syncthreads();   // stage buffers dead; reuse as fp32 planes

    // plane layout: k plane at float offset 0, p plane at 8704; row stride 68
    float* sp = (float*)sm + (size_t)isH * 8704;
#pragma unroll
    for (int mb = 0; mb < 2; mb++)
#pragma unroll
        for (int nb = 0; nb < 8; nb++)
#pragma unroll
            for (int half = 0; half < 2; half++) {
                const int row = 32 * wm + 16 * mb + 8 * half + gq;
                const int col = 8 * nb + 2 * tq;
                sp[row * 68 + col    ] = acc[mb][nb][2 * half];
                sp[row * 68 + col + 1] = acc[mb][nb][2 * half + 1];
            }
    __syncthreads();

    const float2* sK = (const float2*)sm;          // row stride 34 (float2)
    const float2* sP = (const float2*)sm + 4352;   // 8704 floats / 2
    const float2* bz2 = (const float2*)(bz + colBase);
    const float2* bh2 = (const float2*)(bh + colBase);

#pragma unroll
    for (int i = 0; i < 16; i++) {
        const int g   = i * 256 + tid;     // 0..4095
        const int row = g >> 5;
        const int seg = g & 31;
        float2 kk = sK[row * 34 + seg];
        float2 pp = sP[row * 34 + seg];
        float2 bzv = bz2[seg];
        float2 bhv = bh2[seg];
        const float kv0 = kk.x + bzv.x, kv1 = kk.y + bzv.y;
        const float pv0 = pp.x + bhv.x, pv1 = pp.y + bhv.y;
        const float a0 = 1.0f / (1.0f + __expf(kv0));
        const float a1 = 1.0f / (1.0f + __expf(kv1));
        const float z0 = 1.0f / (1.0f + __expf(-kv0));
        const float z1 = 1.0f / (1.0f + __expf(-kv1));
        const float t0 = (pv0 >= 0.f) ? (pv0 + 0.5f) : (1.0f / (1.0f + __expf(-pv0)));
        const float t1 = (pv1 >= 0.f) ? (pv1 + 0.5f) : (1.0f / (1.0f + __expf(-pv1)));
        float4 v; v.x = a0; v.y = z0 * t0; v.z = a1; v.w = z1 * t1;
        *(float4*)&g_ab[(size_t)(rowBase + row) * Hn + colBase + 2 * seg] = v;
    }
}

// --------- single-pass scan, warp-parallel decoupled lookback ---------------
__global__ __launch_bounds__(512)
void scan_fused(int layer, float* __restrict__ out, float* __restrict__ finalDst)
{
    const int h = threadIdx.x;
    const int c = blockIdx.x;
    const int b = blockIdx.y;
    const int lane = h & 31;
    const size_t base = ((size_t)b * Ss + (size_t)c * TLEN2) * Hn + h;

    float2 v[TLEN2];
#pragma unroll
    for (int t = 0; t < TLEN2; t++)
        v[t] = __ldcs(&g_ab[base + (size_t)t * Hn]);

    float A = 1.f, Bv = 0.f;
#pragma unroll
    for (int t = 0; t < TLEN2; t++) {
        Bv = fmaf(v[t].x, Bv, v[t].y);
        A *= v[t].x;
    }

    const int cidx = b * CHUNKS2 + c;
    __shared__ int s_n, s_f2;
    float hstart;

    if (c == 0) {
        hstart = 0.5f;
        float2 pub; pub.x = 0.f; pub.y = fmaf(A, hstart, Bv);
        __stcg(&g_inc[layer][(size_t)cidx * Hn + h], pub);
        __threadfence();
        __syncthreads();
        if (h == 0) atomicExch(&g_fl[layer][cidx], 2);
    } else {
        float2 pub; pub.x = A; pub.y = Bv;
        __stcg(&g_loc[layer][(size_t)cidx * Hn + h], pub);
        __threadfence();
        __syncthreads();
        if (h == 0) atomicExch(&g_fl[layer][cidx], 1);

        float alpha = 1.f, beta = 0.f;
        int p = c - 1;
        for (;;) {
            if (h < 32) {
                int rel = p - lane;
                int f = 0;
                if (rel >= 0) f = atomicAdd(&g_fl[layer][b * CHUNKS2 + rel], 0);
                unsigned m0 = __ballot_sync(0xffffffffu, f == 0);
                unsigned m2 = __ballot_sync(0xffffffffu, f == 2);
                int n = m0 ? (__ffs(m0) - 1) : 32;
                unsigned lim = (n >= 32) ? 0xffffffffu : ((1u << n) - 1u);
                unsigned m2v = m2 & lim;
                int f2 = m2v ? (__ffs(m2v) - 1) : -1;
                if (lane == 0) { s_n = n; s_f2 = f2; }
            }
            __syncthreads();
            const int n = s_n, f2 = s_f2;
            __syncthreads();

            if (f2 >= 0) {
                for (int l = 0; l < f2; l++) {
                    float2 pv = __ldcg(&g_loc[layer][(size_t)(b * CHUNKS2 + p - l) * Hn + h]);
                    beta  = fmaf(alpha, pv.y, beta);
                    alpha *= pv.x;
                }
                float2 iv = __ldcg(&g_inc[layer][(size_t)(b * CHUNKS2 + p - f2) * Hn + h]);
                hstart = fmaf(alpha, iv.y, beta);
                break;
            }
            for (int l = 0; l < n; l++) {
                float2 pv = __ldcg(&g_loc[layer][(size_t)(b * CHUNKS2 + p - l) * Hn + h]);
                beta  = fmaf(alpha, pv.y, beta);
                alpha *= pv.x;
            }
            p -= n;
        }

        float2 pub2; pub2.x = 0.f; pub2.y = fmaf(A, hstart, Bv);
        __stcg(&g_inc[layer][(size_t)cidx * Hn + h], pub2);
        __threadfence();
        __syncthreads();
        if (h == 0) atomicExch(&g_fl[layer][cidx], 2);
    }

    float hv = hstart;
    if (layer == 0) {
#pragma unroll
        for (int t = 0; t < TLEN2; t++) {
            hv = fmaf(v[t].x, hv, v[t].y);
            g_xh[base + (size_t)t * Hn] = __float2half(hv);
        }
    } else {
#pragma unroll
        for (int t = 0; t < TLEN2; t++) {
            hv = fmaf(v[t].x, hv, v[t].y);
            __stcs(&out[base + (size_t)t * Hn], hv);
        }
    }
    if (c == CHUNKS2 - 1)
        finalDst[b * Hn + h] = hv;
}

// --------------------------------- launch ----------------------------------
extern "C" void kernel_launch(void* const* d_in, const int* in_sizes, int n_in,
                              void* d_out, int out_size)
{
    const float* x   = (const float*)d_in[0];
    const float* wz0 = (const float*)d_in[1];
    const float* bz0 = (const float*)d_in[2];
    const float* wh0 = (const float*)d_in[3];
    const float* bh0 = (const float*)d_in[4];
    const float* wz1 = (const float*)d_in[5];
    const float* bz1 = (const float*)d_in[6];
    const float* wh1 = (const float*)d_in[7];
    const float* bh1 = (const float*)d_in[8];

    float* out    = (float*)d_out;
    float* finals = out + (size_t)Mtot * Hn;

    static int smem_set = 0;
    if (!smem_set) {
        cudaFuncSetAttribute(gemm_mma, cudaFuncAttributeMaxDynamicSharedMemorySize,
                             SMEM_BYTES);
        smem_set = 1;
    }

    clear_flags<<<(2 * Bb * CHUNKS2 + 255) / 256, 256>>>();
    conv_x_kern<<<(Mtot * Kd / 4) / 256, 256>>>(x);
    conv_w_all<<<dim3((Kd * Hn / 4) / 256, 4), 256>>>(wz0, wh0, wz1, wh1);

    dim3 gg(Hn / 64, Mtot / 128);    // (8, 256)
    dim3 sg(CHUNKS2, Bb);            // (256, 8)

    gemm_mma<<<gg, 256, SMEM_BYTES>>>(0, bz0, bh0);
    scan_fused<<<sg, Hn>>>(0, nullptr, finals);

    gemm_mma<<<gg, 256, SMEM_BYTES>>>(1, bz1, bh1);
    scan_fused<<<sg, Hn>>>(1, out, finals + Bb * Hn);
}

// round 10
// speedup vs baseline: 1.1809x; 1.1809x over previous
#include <cuda_runtime.h>
#include <cuda_fp16.h>
#include <math.h>
#include <stdint.h>

#define Bb 8
#define Ss 4096
#define Hn 512
#define Kd 512
#define Mtot (Bb*Ss)          // 32768
#define RYT 256               // row tiles (128 rows each)
#define CXT 8                 // col tiles (64 cols each)

// ------------------------- scratch (device globals) -------------------------
__device__ __align__(256) __half  g_x0[(size_t)Mtot*Kd];   // fp16(x)
__device__ __align__(256) __half  g_xh[(size_t)Mtot*Kd];   // layer-0 hidden (fp16)
__device__ __align__(256) float2  g_loc[2][RYT*Hn];        // per-CTA composed (A,B)
__device__ __align__(256) float   g_inc[2][RYT*Hn];        // per-CTA h_end
__device__ __align__(256) int     g_fl [2][RYT*CXT];
__device__ int g_tick[2];
// 0: wz0, 1: wh0, 2: wz1, 3: wh1 (fp16)
__device__ __align__(256) __half  g_w[4][(size_t)Kd*Hn];

// ------------------------------ helpers ------------------------------------
__device__ __forceinline__ uint32_t s2u(const void* p) {
    uint32_t a;
    asm("{ .reg .u64 t; cvta.to.shared.u64 t, %1; cvt.u32.u64 %0, t; }"
        : "=r"(a) : "l"(p));
    return a;
}

__device__ __forceinline__ void cpa16(uint32_t dst, const void* src) {
    asm volatile("cp.async.cg.shared.global [%0], [%1], 16;" :: "r"(dst), "l"(src));
}

__device__ __forceinline__ void mma_f16(float* d, const uint32_t* a,
                                        uint32_t b0, uint32_t b1) {
    asm volatile(
        "mma.sync.aligned.m16n8k16.row.col.f32.f16.f16.f32 "
        "{%0,%1,%2,%3}, {%4,%5,%6,%7}, {%8,%9}, {%0,%1,%2,%3};"
        : "+f"(d[0]), "+f"(d[1]), "+f"(d[2]), "+f"(d[3])
        : "r"(a[0]), "r"(a[1]), "r"(a[2]), "r"(a[3]), "r"(b0), "r"(b1));
}

__device__ __forceinline__ void ldsm4(uint32_t* r, uint32_t addr) {
    asm volatile("ldmatrix.sync.aligned.m8n8.x4.shared.b16 {%0,%1,%2,%3}, [%4];"
        : "=r"(r[0]), "=r"(r[1]), "=r"(r[2]), "=r"(r[3]) : "r"(addr));
}

// ------------------------------- setup kernels -----------------------------
__global__ void clear_state()
{
    int i = blockIdx.x * blockDim.x + threadIdx.x;
    if (i < 2 * RYT * CXT) ((int*)g_fl)[i] = 0;
    if (i < 2) g_tick[i] = 0;
}

__global__ void conv_x_kern(const float* __restrict__ src) {
    int i = blockIdx.x * blockDim.x + threadIdx.x;   // over Mtot*Kd/4
    float4 v = ((const float4*)src)[i];
    __half2 p0 = __floats2half2_rn(v.x, v.y);
    __half2 p1 = __floats2half2_rn(v.z, v.w);
    ((__half2*)g_x0)[2*i  ] = p0;
    ((__half2*)g_x0)[2*i+1] = p1;
}

__global__ void conv_w_all(const float* __restrict__ w0, const float* __restrict__ w1,
                           const float* __restrict__ w2, const float* __restrict__ w3) {
    const float* srcs[4] = {w0, w1, w2, w3};
    const int wsel = blockIdx.y;
    int i = blockIdx.x * blockDim.x + threadIdx.x;   // over Kd*Hn/4
    float4 v = ((const float4*)srcs[wsel])[i];
    __half2 p0 = __floats2half2_rn(v.x, v.y);
    __half2 p1 = __floats2half2_rn(v.z, v.w);
    ((__half2*)g_w[wsel])[2*i  ] = p0;
    ((__half2*)g_w[wsel])[2*i+1] = p1;
}

// ---------------------- fused dual GEMM + scan kernel -----------------------
// Ticket-ordered tiles: ticket t -> ry = t/8 (row tile), cx = t%8 (col tile).
// Mainloop identical to R8 (128Mx64N, 4-stage cp.async, 2 CTAs/SM).
// Epilogue: activations -> smem planes; chunk+CTA affine compose; decoupled
// lookback along ry (per batch of 32 row-tiles); emit hidden states directly.
#define KC 32
#define STAGES 4
#define STAGE_BYTES 20480
#define SMEM_BYTES (STAGES*STAGE_BYTES)
#define NCHUNK (Kd/KC)   // 16

__device__ __forceinline__ void load_stage(uint32_t sb,
    const __half* Ax, const __half* Wz, const __half* Wh,
    int rowBase, int colBase, int kOff, int tid)
{
#pragma unroll
    for (int i = 0; i < 2; i++) {
        int idx = tid + i * 256;         // 0..511
        int r   = idx >> 2;              // 0..127
        int seg = idx & 3;
        const __half* src = Ax + (size_t)(rowBase + r) * Kd + kOff + seg * 8;
        cpa16(sb + r * 80 + seg * 16, src);
    }
#pragma unroll
    for (int i = 0; i < 2; i++) {
        int idx  = tid + i * 256;        // 0..511
        int tile = idx >> 8;             // 0=Wz, 1=Wh
        int r    = (idx >> 2) & 63;
        int seg  = idx & 3;
        const __half* src = (tile ? Wh : Wz)
            + (size_t)(colBase + r) * Kd + kOff + seg * 8;
        cpa16(sb + 10240 + tile * 5120 + r * 80 + seg * 16, src);
    }
}

__global__ __launch_bounds__(256, 2)
void gemm_scan(int layer, const float* __restrict__ bz, const float* __restrict__ bh,
               float* __restrict__ out, float* __restrict__ finals)
{
    extern __shared__ __align__(16) char sm[];
    const uint32_t sb = s2u(sm);
    __shared__ int s_tick, s_n, s_f2;

    const int tid  = threadIdx.x;
    const int lane = tid & 31;
    const int wid  = tid >> 5;
    const int gq   = lane >> 2;
    const int tq   = lane & 3;
    const int wm   = wid & 3;
    const int wn   = wid >> 2;

    if (tid == 0) s_tick = atomicAdd(&g_tick[layer], 1);
    __syncthreads();
    const int tk = s_tick;
    const int ry = tk >> 3;          // 0..255
    const int cx = tk & 7;           // 0..7
    const int rowBase = ry * 128;
    const int colBase = cx * 64;
    const int batchBase = ry & ~31;  // first row-tile of this batch

    const __half* Ain = layer ? g_xh : g_x0;
    const __half* Wz  = g_w[2 * layer + 0];
    const __half* Wh  = g_w[2 * layer + 1];

    const uint32_t aLane = (uint32_t)((32 * wm + (lane & 15)) * 80 + ((lane >> 4) << 4));
    const uint32_t bLane = (uint32_t)(((32 * wn) + ((lane >> 4) << 3) + (lane & 7)) * 80
                                      + (((lane >> 3) & 1) << 4));

    float accZ[2][4][4];
    float accH[2][4][4];
#pragma unroll
    for (int mb = 0; mb < 2; mb++)
#pragma unroll
        for (int nb = 0; nb < 4; nb++)
#pragma unroll
            for (int r = 0; r < 4; r++) { accZ[mb][nb][r] = 0.f; accH[mb][nb][r] = 0.f; }

#pragma unroll
    for (int s = 0; s < 3; s++) {
        load_stage(sb + s * STAGE_BYTES, Ain, Wz, Wh, rowBase, colBase, s * KC, tid);
        asm volatile("cp.async.commit_group;" ::: "memory");
    }

    for (int c = 0; c < NCHUNK; c++) {
        if (c < NCHUNK - 2)       asm volatile("cp.async.wait_group 2;" ::: "memory");
        else if (c == NCHUNK - 2) asm volatile("cp.async.wait_group 1;" ::: "memory");
        else                      asm volatile("cp.async.wait_group 0;" ::: "memory");
        __syncthreads();

        if (c + 3 < NCHUNK) {
            load_stage(sb + ((c + 3) % STAGES) * STAGE_BYTES, Ain, Wz, Wh,
                       rowBase, colBase, (c + 3) * KC, tid);
            asm volatile("cp.async.commit_group;" ::: "memory");
        }

        const uint32_t stg = sb + (c % STAGES) * STAGE_BYTES;
        const uint32_t aA  = stg +     0 + aLane;
        const uint32_t bZ  = stg + 10240 + bLane;
        const uint32_t bH  = stg + 15360 + bLane;

#pragma unroll
        for (int ks = 0; ks < 2; ks++) {
            const uint32_t kb = (uint32_t)(ks * 32);
            uint32_t Af[2][4], zz[2][4], hh[2][4];
#pragma unroll
            for (int mb = 0; mb < 2; mb++)
                ldsm4(Af[mb], aA + mb * (16 * 80) + kb);
#pragma unroll
            for (int p = 0; p < 2; p++) {
                ldsm4(zz[p], bZ + p * (16 * 80) + kb);
                ldsm4(hh[p], bH + p * (16 * 80) + kb);
            }
#pragma unroll
            for (int p = 0; p < 2; p++)
#pragma unroll
                for (int q = 0; q < 2; q++)
#pragma unroll
                    for (int mb = 0; mb < 2; mb++) {
                        const int nb = 2 * p + q;
                        mma_f16(accZ[mb][nb], Af[mb], zz[p][2*q], zz[p][2*q+1]);
                        mma_f16(accH[mb][nb], Af[mb], hh[p][2*q], hh[p][2*q+1]);
                    }
        }
    }

    // ==================== epilogue: activation + fused scan =================
    __syncthreads();   // stage buffers dead; reuse smem

    float* aP  = (float*)sm;          // 128 x 64, stride 68  (34816 B)
    float* bP  = aP + 8704;           // 128 x 64, stride 68
    float* sA  = bP + 8704;           // 8 x 64 chunk A
    float* sB  = sA + 512;            // 8 x 64 chunk B
    float* hIn = sB + 512;            // 8 x 64 chunk entry h

    // 1) activation -> planes
#pragma unroll
    for (int mb = 0; mb < 2; mb++)
#pragma unroll
        for (int nb = 0; nb < 4; nb++) {
            const int col = 32 * wn + 8 * nb + 2 * tq;
            const float bz0 = bz[colBase + col], bz1 = bz[colBase + col + 1];
            const float bh0 = bh[colBase + col], bh1 = bh[colBase + col + 1];
#pragma unroll
            for (int half = 0; half < 2; half++) {
                const int row = 32 * wm + 16 * mb + 8 * half + gq;
                const float kv0 = accZ[mb][nb][2 * half]     + bz0;
                const float kv1 = accZ[mb][nb][2 * half + 1] + bz1;
                const float pv0 = accH[mb][nb][2 * half]     + bh0;
                const float pv1 = accH[mb][nb][2 * half + 1] + bh1;
                const float a0 = 1.0f / (1.0f + __expf(kv0));
                const float a1 = 1.0f / (1.0f + __expf(kv1));
                const float z0 = 1.0f / (1.0f + __expf(-kv0));
                const float z1 = 1.0f / (1.0f + __expf(-kv1));
                const float t0 = (pv0 >= 0.f) ? (pv0 + 0.5f) : (1.0f / (1.0f + __expf(-pv0)));
                const float t1 = (pv1 >= 0.f) ? (pv1 + 0.5f) : (1.0f / (1.0f + __expf(-pv1)));
                aP[row * 68 + col    ] = a0;
                aP[row * 68 + col + 1] = a1;
                bP[row * 68 + col    ] = z0 * t0;
                bP[row * 68 + col + 1] = z1 * t1;
            }
        }
    __syncthreads();

    // 2) chunk-local compose (8 chunks x 64 cols; 2 items/thread)
#pragma unroll
    for (int k = 0; k < 2; k++) {
        const int item = tid + k * 256;
        const int j = item >> 6, cc = item & 63;
        float A = 1.f, Bv = 0.f;
#pragma unroll
        for (int t = 0; t < 16; t++) {
            const int row = j * 16 + t;
            const float a = aP[row * 68 + cc];
            const float b = bP[row * 68 + cc];
            Bv = fmaf(a, Bv, b);
            A *= a;
        }
        sA[j * 64 + cc] = A;
        sB[j * 64 + cc] = Bv;
    }
    __syncthreads();

    // 3) CTA compose + publish loc
    if (tid < 64) {
        float A = 1.f, Bv = 0.f;
#pragma unroll
        for (int j = 0; j < 8; j++) {
            Bv = fmaf(sA[j * 64 + tid], Bv, sB[j * 64 + tid]);
            A *= sA[j * 64 + tid];
        }
        float2 pub; pub.x = A; pub.y = Bv;
        __stcg(&g_loc[layer][(size_t)ry * Hn + colBase + tid], pub);
        __threadfence();
    }
    __syncthreads();
    if (tid == 0) atomicExch(&g_fl[layer][ry * 8 + cx], 1);

    // 4) lookback -> hstart (per col, threads 0..63)
    float hstart = 0.5f;
    if (ry != batchBase) {
        float alpha = 1.f, beta = 0.f;
        int p = ry - 1;
        for (;;) {
            if (tid < 32) {
                int rel = p - lane;
                int f = 0;
                if (rel >= batchBase) f = atomicAdd(&g_fl[layer][rel * 8 + cx], 0);
                unsigned m0 = __ballot_sync(0xffffffffu, f == 0);
                unsigned m2 = __ballot_sync(0xffffffffu, f == 2);
                int n = m0 ? (__ffs(m0) - 1) : 32;
                unsigned lim = (n >= 32) ? 0xffffffffu : ((1u << n) - 1u);
                unsigned m2v = m2 & lim;
                int f2 = m2v ? (__ffs(m2v) - 1) : -1;
                if (lane == 0) { s_n = n; s_f2 = f2; }
            }
            __syncthreads();
            const int n = s_n, f2 = s_f2;
            __syncthreads();

            if (f2 >= 0) {
                if (tid < 64) {
                    for (int l = 0; l < f2; l++) {
                        float2 pv = __ldcg(&g_loc[layer][(size_t)(p - l) * Hn + colBase + tid]);
                        beta  = fmaf(alpha, pv.y, beta);
                        alpha *= pv.x;
                    }
                    float iv = __ldcg(&g_inc[layer][(size_t)(p - f2) * Hn + colBase + tid]);
                    hstart = fmaf(alpha, iv, beta);
                }
                break;
            }
            if (tid < 64) {
                for (int l = 0; l < n; l++) {
                    float2 pv = __ldcg(&g_loc[layer][(size_t)(p - l) * Hn + colBase + tid]);
                    beta  = fmaf(alpha, pv.y, beta);
                    alpha *= pv.x;
                }
            }
            p -= n;
            if (p < batchBase) {         // walked past batch base: h0 = 0.5
                if (tid < 64) hstart = fmaf(alpha, 0.5f, beta);
                break;
            }
        }
    }

    // 5) chunk entry states + publish inclusive h_end (+ finals)
    if (tid < 64) {
        float h = hstart;
#pragma unroll
        for (int j = 0; j < 8; j++) {
            hIn[j * 64 + tid] = h;
            h = fmaf(sA[j * 64 + tid], h, sB[j * 64 + tid]);
        }
        __stcg(&g_inc[layer][(size_t)ry * Hn + colBase + tid], h);
        __threadfence();
        if ((ry & 31) == 31)
            finals[(ry >> 5) * Hn + colBase + tid] = h;
    }
    __syncthreads();
    if (tid == 0) atomicExch(&g_fl[layer][ry * 8 + cx], 2);

    // 6) emit hidden states
#pragma unroll
    for (int k = 0; k < 2; k++) {
        const int item = tid + k * 256;
        const int j = item >> 6, cc = item & 63;
        float h = hIn[j * 64 + cc];
        if (layer == 0) {
#pragma unroll
            for (int t = 0; t < 16; t++) {
                const int row = j * 16 + t;
                h = fmaf(aP[row * 68 + cc], h, bP[row * 68 + cc]);
                g_xh[(size_t)(rowBase + row) * Hn + colBase + cc] = __float2half(h);
            }
        } else {
#pragma unroll
            for (int t = 0; t < 16; t++) {
                const int row = j * 16 + t;
                h = fmaf(aP[row * 68 + cc], h, bP[row * 68 + cc]);
                __stcs(&out[(size_t)(rowBase + row) * Hn + colBase + cc], h);
            }
        }
    }
}

// --------------------------------- launch ----------------------------------
extern "C" void kernel_launch(void* const* d_in, const int* in_sizes, int n_in,
                              void* d_out, int out_size)
{
    const float* x   = (const float*)d_in[0];
    const float* wz0 = (const float*)d_in[1];
    const float* bz0 = (const float*)d_in[2];
    const float* wh0 = (const float*)d_in[3];
    const float* bh0 = (const float*)d_in[4];
    const float* wz1 = (const float*)d_in[5];
    const float* bz1 = (const float*)d_in[6];
    const float* wh1 = (const float*)d_in[7];
    const float* bh1 = (const float*)d_in[8];

    float* out    = (float*)d_out;
    float* finals = out + (size_t)Mtot * Hn;

    static int smem_set = 0;
    if (!smem_set) {
        cudaFuncSetAttribute(gemm_scan, cudaFuncAttributeMaxDynamicSharedMemorySize,
                             SMEM_BYTES);
        smem_set = 1;
    }

    clear_state<<<(2 * RYT * CXT + 255) / 256, 256>>>();
    conv_x_kern<<<(Mtot * Kd / 4) / 256, 256>>>(x);
    conv_w_all<<<dim3((Kd * Hn / 4) / 256, 4), 256>>>(wz0, wh0, wz1, wh1);

    gemm_scan<<<RYT * CXT, 256, SMEM_BYTES>>>(0, bz0, bh0, nullptr, finals);
    gemm_scan<<<RYT * CXT, 256, SMEM_BYTES>>>(1, bz1, bh1, out, finals + Bb * Hn);
}

// round 11
// speedup vs baseline: 1.4298x; 1.2108x over previous
#include <cuda_runtime.h>
#include <cuda_fp16.h>
#include <math.h>
#include <stdint.h>

#define Bb 8
#define Ss 4096
#define Hn 512
#define Kd 512
#define Mtot (Bb*Ss)          // 32768
#define RYT 256               // row tiles (128 rows)
#define CXT 8                 // col tiles (64 cols)
#define NCHUNK 16             // K chunks of 32

// Tiled gmem images matching smem layout: 80B (40-half) padded rows.
// A block: 128 rows x 40 halves = 5120 halves (10240 B) per (ry, chunk).
// W block: 64 rows x 40 halves = 2560 halves (5120 B) per (mat, cx, chunk).
#define ABLK_H 5120
#define WBLK_H 2560

__device__ __align__(256) __half  g_x0[(size_t)RYT*NCHUNK*ABLK_H];
__device__ __align__(256) __half  g_xh[(size_t)RYT*NCHUNK*ABLK_H];
__device__ __align__(256) __half  g_w [(size_t)4*CXT*NCHUNK*WBLK_H];
__device__ __align__(256) float2  g_loc[2][RYT*Hn];
__device__ __align__(256) float   g_inc[2][RYT*Hn];
__device__ __align__(256) int     g_fl [2][RYT*CXT];
__device__ int g_tick[2];

// ------------------------------ helpers ------------------------------------
__device__ __forceinline__ uint32_t s2u(const void* p) {
    uint32_t a;
    asm("{ .reg .u64 t; cvta.to.shared.u64 t, %1; cvt.u32.u64 %0, t; }"
        : "=r"(a) : "l"(p));
    return a;
}

__device__ __forceinline__ void mma_f16(float* d, const uint32_t* a,
                                        uint32_t b0, uint32_t b1) {
    asm volatile(
        "mma.sync.aligned.m16n8k16.row.col.f32.f16.f16.f32 "
        "{%0,%1,%2,%3}, {%4,%5,%6,%7}, {%8,%9}, {%0,%1,%2,%3};"
        : "+f"(d[0]), "+f"(d[1]), "+f"(d[2]), "+f"(d[3])
        : "r"(a[0]), "r"(a[1]), "r"(a[2]), "r"(a[3]), "r"(b0), "r"(b1));
}

__device__ __forceinline__ void ldsm4(uint32_t* r, uint32_t addr) {
    asm volatile("ldmatrix.sync.aligned.m8n8.x4.shared.b16 {%0,%1,%2,%3}, [%4];"
        : "=r"(r[0]), "=r"(r[1]), "=r"(r[2]), "=r"(r[3]) : "r"(addr));
}

__device__ __forceinline__ void mbar_init(uint32_t m, uint32_t cnt) {
    asm volatile("mbarrier.init.shared.b64 [%0], %1;" :: "r"(m), "r"(cnt) : "memory");
}
__device__ __forceinline__ void mbar_expect(uint32_t m, uint32_t bytes) {
    asm volatile("mbarrier.arrive.expect_tx.shared.b64 _, [%0], %1;"
                 :: "r"(m), "r"(bytes) : "memory");
}
__device__ __forceinline__ void mbar_wait(uint32_t m, uint32_t parity) {
    asm volatile(
        "{\n\t.reg .pred P1;\n\t"
        "WL%=:\n\t"
        "mbarrier.try_wait.parity.acquire.cta.shared::cta.b64 P1, [%0], %1, 0x989680;\n\t"
        "@P1 bra.uni WD%=;\n\t"
        "bra.uni WL%=;\n\t"
        "WD%=:\n\t}"
        :: "r"(m), "r"(parity) : "memory");
}
__device__ __forceinline__ void bulkcp(uint32_t dst, const void* gsrc,
                                       uint32_t bytes, uint32_t mbar) {
    uint64_t ga;
    asm volatile("cvta.to.global.u64 %0, %1;" : "=l"(ga) : "l"(gsrc));
    asm volatile(
        "cp.async.bulk.shared::cluster.global.mbarrier::complete_tx::bytes "
        "[%0], [%1], %2, [%3];"
        :: "r"(dst), "l"(ga), "r"(bytes), "r"(mbar) : "memory");
}

// ------------------------------- setup kernels -----------------------------
__global__ void clear_state()
{
    int i = blockIdx.x * blockDim.x + threadIdx.x;
    if (i < 2 * RYT * CXT) ((int*)g_fl)[i] = 0;
    if (i < 2) g_tick[i] = 0;
}

// x -> tiled fp16 image
__global__ void conv_x_kern(const float* __restrict__ src) {
    int i = blockIdx.x * blockDim.x + threadIdx.x;   // over Mtot*Kd/4
    float4 v = ((const float4*)src)[i];
    __half2 p0 = __floats2half2_rn(v.x, v.y);
    __half2 p1 = __floats2half2_rn(v.z, v.w);
    const int m = i >> 7;
    const int k = (i & 127) * 4;
    const int ry = m >> 7, c = k >> 5, row = m & 127, col = k & 31;
    __half2* dst = (__half2*)&g_x0[(size_t)(ry * NCHUNK + c) * ABLK_H + row * 40 + col];
    dst[0] = p0; dst[1] = p1;
}

// weights -> tiled fp16 image (mat = blockIdx.y: 0 wz0, 1 wh0, 2 wz1, 3 wh1)
__global__ void conv_w_all(const float* __restrict__ w0, const float* __restrict__ w1,
                           const float* __restrict__ w2, const float* __restrict__ w3) {
    const float* srcs[4] = {w0, w1, w2, w3};
    const int mat = blockIdx.y;
    int i = blockIdx.x * blockDim.x + threadIdx.x;   // over Kd*Hn/4
    float4 v = ((const float4*)srcs[mat])[i];
    __half2 p0 = __floats2half2_rn(v.x, v.y);
    __half2 p1 = __floats2half2_rn(v.z, v.w);
    const int h = i >> 7;
    const int k = (i & 127) * 4;
    const int cx = h >> 6, c = k >> 5, row = h & 63, col = k & 31;
    __half2* dst = (__half2*)&g_w[(size_t)(((mat * CXT + cx) * NCHUNK) + c) * WBLK_H
                                  + row * 40 + col];
    dst[0] = p0; dst[1] = p1;
}

// ---------------------- fused dual GEMM + scan kernel -----------------------
#define STAGE_BYTES 20480     // A 10240 + WZ 5120 + WH 5120
#define STAGES 4
#define SMEM_BYTES (STAGES*STAGE_BYTES)   // 81920

__global__ __launch_bounds__(256, 2)
void gemm_scan(int layer, const float* __restrict__ bz, const float* __restrict__ bh,
               float* __restrict__ out, float* __restrict__ finals)
{
    extern __shared__ __align__(16) char sm[];
    const uint32_t sb = s2u(sm);
    __shared__ __align__(8) uint64_t s_mbar[STAGES];
    __shared__ int s_tick, s_n, s_f2;

    const int tid  = threadIdx.x;
    const int lane = tid & 31;
    const int wid  = tid >> 5;
    const int gq   = lane >> 2;
    const int tq   = lane & 3;
    const int wm   = wid & 3;
    const int wn   = wid >> 2;
    const uint32_t mb0 = s2u(s_mbar);

    if (tid == 0) {
        s_tick = atomicAdd(&g_tick[layer], 1);
#pragma unroll
        for (int s = 0; s < STAGES; s++) mbar_init(mb0 + 8 * s, 1);
    }
    __syncthreads();
    const int tk = s_tick;
    const int ry = tk >> 3;
    const int cx = tk & 7;
    const int rowBase = ry * 128;
    const int colBase = cx * 64;
    const int batchBase = ry & ~31;

    const __half* Ab  = (layer ? g_xh : g_x0) + (size_t)ry * NCHUNK * ABLK_H;
    const __half* Wzb = g_w + (size_t)((2 * layer)     * CXT + cx) * NCHUNK * WBLK_H;
    const __half* Whb = g_w + (size_t)((2 * layer + 1) * CXT + cx) * NCHUNK * WBLK_H;

    const uint32_t aLane = (uint32_t)((32 * wm + (lane & 15)) * 80 + ((lane >> 4) << 4));
    const uint32_t bLane = (uint32_t)(((32 * wn) + ((lane >> 4) << 3) + (lane & 7)) * 80
                                      + (((lane >> 3) & 1) << 4));

    float accZ[2][4][4];
    float accH[2][4][4];
#pragma unroll
    for (int mbi = 0; mbi < 2; mbi++)
#pragma unroll
        for (int nb = 0; nb < 4; nb++)
#pragma unroll
            for (int r = 0; r < 4; r++) { accZ[mbi][nb][r] = 0.f; accH[mbi][nb][r] = 0.f; }

    // prologue: chunks 0..2
    if (tid == 0) {
#pragma unroll
        for (int s = 0; s < 3; s++) {
            const uint32_t st = sb + s * STAGE_BYTES;
            const uint32_t m  = mb0 + 8 * s;
            mbar_expect(m, STAGE_BYTES);
            bulkcp(st,         Ab  + (size_t)s * ABLK_H, 10240, m);
            bulkcp(st + 10240, Wzb + (size_t)s * WBLK_H,  5120, m);
            bulkcp(st + 15360, Whb + (size_t)s * WBLK_H,  5120, m);
        }
    }

    for (int c = 0; c < NCHUNK; c++) {
        mbar_wait(mb0 + 8 * (c & 3), (c >> 2) & 1);

        const uint32_t stg = sb + (c & 3) * STAGE_BYTES;
        const uint32_t aA  = stg +     0 + aLane;
        const uint32_t bZ  = stg + 10240 + bLane;
        const uint32_t bH  = stg + 15360 + bLane;

#pragma unroll
        for (int ks = 0; ks < 2; ks++) {
            const uint32_t kb = (uint32_t)(ks * 32);
            uint32_t Af[2][4], zz[2][4], hh[2][4];
#pragma unroll
            for (int mbi = 0; mbi < 2; mbi++)
                ldsm4(Af[mbi], aA + mbi * (16 * 80) + kb);
#pragma unroll
            for (int p = 0; p < 2; p++) {
                ldsm4(zz[p], bZ + p * (16 * 80) + kb);
                ldsm4(hh[p], bH + p * (16 * 80) + kb);
            }
#pragma unroll
            for (int p = 0; p < 2; p++)
#pragma unroll
                for (int q = 0; q < 2; q++)
#pragma unroll
                    for (int mbi = 0; mbi < 2; mbi++) {
                        const int nb = 2 * p + q;
                        mma_f16(accZ[mbi][nb], Af[mbi], zz[p][2*q], zz[p][2*q+1]);
                        mma_f16(accH[mbi][nb], Af[mbi], hh[p][2*q], hh[p][2*q+1]);
                    }
        }

        __syncthreads();  // all warps done with chunk c (and earlier)
        if (tid == 0 && c + 3 < NCHUNK) {
            const int nc = c + 3;
            const uint32_t st = sb + (nc & 3) * STAGE_BYTES;
            const uint32_t m  = mb0 + 8 * (nc & 3);
            mbar_expect(m, STAGE_BYTES);
            bulkcp(st,         Ab  + (size_t)nc * ABLK_H, 10240, m);
            bulkcp(st + 10240, Wzb + (size_t)nc * WBLK_H,  5120, m);
            bulkcp(st + 15360, Whb + (size_t)nc * WBLK_H,  5120, m);
        }
    }

    // ==================== epilogue: activation + fused scan =================
    float* aP  = (float*)sm;          // 128 x 64, stride 68
    float* bP  = aP + 8704;
    float* sA  = bP + 8704;           // 8 x 64
    float* sB  = sA + 512;
    float* hIn = sB + 512;

    // 1) activation -> planes   (a = sigmoid(-k), z = 1-a, b = z*g(p))
#pragma unroll
    for (int mbi = 0; mbi < 2; mbi++)
#pragma unroll
        for (int nb = 0; nb < 4; nb++) {
            const int col = 32 * wn + 8 * nb + 2 * tq;
            const float bz0 = bz[colBase + col], bz1 = bz[colBase + col + 1];
            const float bh0 = bh[colBase + col], bh1 = bh[colBase + col + 1];
#pragma unroll
            for (int half = 0; half < 2; half++) {
                const int row = 32 * wm + 16 * mbi + 8 * half + gq;
                const float kv0 = accZ[mbi][nb][2 * half]     + bz0;
                const float kv1 = accZ[mbi][nb][2 * half + 1] + bz1;
                const float pv0 = accH[mbi][nb][2 * half]     + bh0;
                const float pv1 = accH[mbi][nb][2 * half + 1] + bh1;
                const float a0 = 1.0f / (1.0f + __expf(kv0));
                const float a1 = 1.0f / (1.0f + __expf(kv1));
                const float z0 = 1.0f - a0;
                const float z1 = 1.0f - a1;
                const float t0 = (pv0 >= 0.f) ? (pv0 + 0.5f) : (1.0f / (1.0f + __expf(-pv0)));
                const float t1 = (pv1 >= 0.f) ? (pv1 + 0.5f) : (1.0f / (1.0f + __expf(-pv1)));
                aP[row * 68 + col    ] = a0;
                aP[row * 68 + col + 1] = a1;
                bP[row * 68 + col    ] = z0 * t0;
                bP[row * 68 + col + 1] = z1 * t1;
            }
        }
    __syncthreads();

    // 2) chunk-local compose
#pragma unroll
    for (int k = 0; k < 2; k++) {
        const int item = tid + k * 256;
        const int j = item >> 6, cc = item & 63;
        float A = 1.f, Bv = 0.f;
#pragma unroll
        for (int t = 0; t < 16; t++) {
            const int row = j * 16 + t;
            const float a = aP[row * 68 + cc];
            const float b = bP[row * 68 + cc];
            Bv = fmaf(a, Bv, b);
            A *= a;
        }
        sA[j * 64 + cc] = A;
        sB[j * 64 + cc] = Bv;
    }
    __syncthreads();

    // 3) CTA compose + publish loc
    if (tid < 64) {
        float A = 1.f, Bv = 0.f;
#pragma unroll
        for (int j = 0; j < 8; j++) {
            Bv = fmaf(sA[j * 64 + tid], Bv, sB[j * 64 + tid]);
            A *= sA[j * 64 + tid];
        }
        float2 pub; pub.x = A; pub.y = Bv;
        __stcg(&g_loc[layer][(size_t)ry * Hn + colBase + tid], pub);
        __threadfence();
    }
    __syncthreads();
    if (tid == 0) atomicExch(&g_fl[layer][ry * 8 + cx], 1);

    // 4) lookback
    float hstart = 0.5f;
    if (ry != batchBase) {
        float alpha = 1.f, beta = 0.f;
        int p = ry - 1;
        for (;;) {
            if (tid < 32) {
                int rel = p - lane;
                int f = 0;
                if (rel >= batchBase) f = atomicAdd(&g_fl[layer][rel * 8 + cx], 0);
                unsigned m0 = __ballot_sync(0xffffffffu, f == 0);
                unsigned m2 = __ballot_sync(0xffffffffu, f == 2);
                int n = m0 ? (__ffs(m0) - 1) : 32;
                unsigned lim = (n >= 32) ? 0xffffffffu : ((1u << n) - 1u);
                unsigned m2v = m2 & lim;
                int f2 = m2v ? (__ffs(m2v) - 1) : -1;
                if (lane == 0) { s_n = n; s_f2 = f2; }
            }
            __syncthreads();
            const int n = s_n, f2 = s_f2;
            __syncthreads();

            if (f2 >= 0) {
                if (tid < 64) {
                    for (int l = 0; l < f2; l++) {
                        float2 pv = __ldcg(&g_loc[layer][(size_t)(p - l) * Hn + colBase + tid]);
                        beta  = fmaf(alpha, pv.y, beta);
                        alpha *= pv.x;
                    }
                    float iv = __ldcg(&g_inc[layer][(size_t)(p - f2) * Hn + colBase + tid]);
                    hstart = fmaf(alpha, iv, beta);
                }
                break;
            }
            if (tid < 64) {
                for (int l = 0; l < n; l++) {
                    float2 pv = __ldcg(&g_loc[layer][(size_t)(p - l) * Hn + colBase + tid]);
                    beta  = fmaf(alpha, pv.y, beta);
                    alpha *= pv.x;
                }
            }
            p -= n;
            if (p < batchBase) {
                if (tid < 64) hstart = fmaf(alpha, 0.5f, beta);
                break;
            }
        }
    }

    // 5) chunk entry states + publish inclusive
    if (tid < 64) {
        float h = hstart;
#pragma unroll
        for (int j = 0; j < 8; j++) {
            hIn[j * 64 + tid] = h;
            h = fmaf(sA[j * 64 + tid], h, sB[j * 64 + tid]);
        }
        __stcg(&g_inc[layer][(size_t)ry * Hn + colBase + tid], h);
        __threadfence();
        if ((ry & 31) == 31)
            finals[(ry >> 5) * Hn + colBase + tid] = h;
    }
    __syncthreads();
    if (tid == 0) atomicExch(&g_fl[layer][ry * 8 + cx], 2);

    // 6) emit hidden states
#pragma unroll
    for (int k = 0; k < 2; k++) {
        const int item = tid + k * 256;
        const int j = item >> 6, cc = item & 63;
        float h = hIn[j * 64 + cc];
        if (layer == 0) {
            // write into tiled image for layer-1 GEMM
            __half* dst = g_xh + (size_t)(ry * NCHUNK + 2 * cx + (cc >> 5)) * ABLK_H
                          + (cc & 31);
#pragma unroll
            for (int t = 0; t < 16; t++) {
                const int row = j * 16 + t;
                h = fmaf(aP[row * 68 + cc], h, bP[row * 68 + cc]);
                dst[row * 40] = __float2half(h);
            }
        } else {
#pragma unroll
            for (int t = 0; t < 16; t++) {
                const int row = j * 16 + t;
                h = fmaf(aP[row * 68 + cc], h, bP[row * 68 + cc]);
                __stcs(&out[(size_t)(rowBase + row) * Hn + colBase + cc], h);
            }
        }
    }
}

// --------------------------------- launch ----------------------------------
extern "C" void kernel_launch(void* const* d_in, const int* in_sizes, int n_in,
                              void* d_out, int out_size)
{
    const float* x   = (const float*)d_in[0];
    const float* wz0 = (const float*)d_in[1];
    const float* bz0 = (const float*)d_in[2];
    const float* wh0 = (const float*)d_in[3];
    const float* bh0 = (const float*)d_in[4];
    const float* wz1 = (const float*)d_in[5];
    const float* bz1 = (const float*)d_in[6];
    const float* wh1 = (const float*)d_in[7];
    const float* bh1 = (const float*)d_in[8];

    float* out    = (float*)d_out;
    float* finals = out + (size_t)Mtot * Hn;

    static int smem_set = 0;
    if (!smem_set) {
        cudaFuncSetAttribute(gemm_scan, cudaFuncAttributeMaxDynamicSharedMemorySize,
                             SMEM_BYTES);
        smem_set = 1;
    }

    clear_state<<<(2 * RYT * CXT + 255) / 256, 256>>>();
    conv_x_kern<<<(Mtot * Kd / 4) / 256, 256>>>(x);
    conv_w_all<<<dim3((Kd * Hn / 4) / 256, 4), 256>>>(wz0, wh0, wz1, wh1);

    gemm_scan<<<RYT * CXT, 256, SMEM_BYTES>>>(0, bz0, bh0, nullptr, finals);
    gemm_scan<<<RYT * CXT, 256, SMEM_BYTES>>>(1, bz1, bh1, out, finals + Bb * Hn);
}

// round 12
// speedup vs baseline: 1.4476x; 1.0124x over previous
#include <cuda_runtime.h>
#include <cuda_fp16.h>
#include <math.h>
#include <stdint.h>

#define Bb 8
#define Ss 4096
#define Hn 512
#define Kd 512
#define Mtot (Bb*Ss)          // 32768
#define RYT 256               // row tiles (128 rows)
#define CXT 8                 // col tiles (64 cols)
#define NCHUNK 16             // K chunks of 32

// Tiled gmem images matching smem layout: 80B (40-half) padded rows.
#define ABLK_H 5120
#define WBLK_H 2560

__device__ __align__(256) __half  g_x0[(size_t)RYT*NCHUNK*ABLK_H];
__device__ __align__(256) __half  g_xh[(size_t)RYT*NCHUNK*ABLK_H];
__device__ __align__(256) __half  g_w [(size_t)4*CXT*NCHUNK*WBLK_H];
__device__ __align__(256) float2  g_loc[2][RYT*Hn];
__device__ __align__(256) float   g_inc[2][RYT*Hn];
__device__ __align__(256) int     g_fl [2][RYT*CXT];
__device__ int g_tick[2];

// ------------------------------ helpers ------------------------------------
__device__ __forceinline__ uint32_t s2u(const void* p) {
    uint32_t a;
    asm("{ .reg .u64 t; cvta.to.shared.u64 t, %1; cvt.u32.u64 %0, t; }"
        : "=r"(a) : "l"(p));
    return a;
}

__device__ __forceinline__ void mma_f16(float* d, const uint32_t* a,
                                        uint32_t b0, uint32_t b1) {
    asm volatile(
        "mma.sync.aligned.m16n8k16.row.col.f32.f16.f16.f32 "
        "{%0,%1,%2,%3}, {%4,%5,%6,%7}, {%8,%9}, {%0,%1,%2,%3};"
        : "+f"(d[0]), "+f"(d[1]), "+f"(d[2]), "+f"(d[3])
        : "r"(a[0]), "r"(a[1]), "r"(a[2]), "r"(a[3]), "r"(b0), "r"(b1));
}

__device__ __forceinline__ void ldsm4(uint32_t* r, uint32_t addr) {
    asm volatile("ldmatrix.sync.aligned.m8n8.x4.shared.b16 {%0,%1,%2,%3}, [%4];"
        : "=r"(r[0]), "=r"(r[1]), "=r"(r[2]), "=r"(r[3]) : "r"(addr));
}

__device__ __forceinline__ void mbar_init(uint32_t m, uint32_t cnt) {
    asm volatile("mbarrier.init.shared.b64 [%0], %1;" :: "r"(m), "r"(cnt) : "memory");
}
__device__ __forceinline__ void mbar_expect(uint32_t m, uint32_t bytes) {
    asm volatile("mbarrier.arrive.expect_tx.shared.b64 _, [%0], %1;"
                 :: "r"(m), "r"(bytes) : "memory");
}
__device__ __forceinline__ void mbar_arrive(uint32_t m) {
    asm volatile("mbarrier.arrive.shared.b64 _, [%0];" :: "r"(m) : "memory");
}
__device__ __forceinline__ void mbar_wait(uint32_t m, uint32_t parity) {
    asm volatile(
        "{\n\t.reg .pred P1;\n\t"
        "WL%=:\n\t"
        "mbarrier.try_wait.parity.acquire.cta.shared::cta.b64 P1, [%0], %1, 0x989680;\n\t"
        "@P1 bra.uni WD%=;\n\t"
        "bra.uni WL%=;\n\t"
        "WD%=:\n\t}"
        :: "r"(m), "r"(parity) : "memory");
}
__device__ __forceinline__ void bulkcp(uint32_t dst, const void* gsrc,
                                       uint32_t bytes, uint32_t mbar) {
    uint64_t ga;
    asm volatile("cvta.to.global.u64 %0, %1;" : "=l"(ga) : "l"(gsrc));
    asm volatile(
        "cp.async.bulk.shared::cluster.global.mbarrier::complete_tx::bytes "
        "[%0], [%1], %2, [%3];"
        :: "r"(dst), "l"(ga), "r"(bytes), "r"(mbar) : "memory");
}

// ------------------------------- setup kernels -----------------------------
__global__ void clear_state()
{
    int i = blockIdx.x * blockDim.x + threadIdx.x;
    if (i < 2 * RYT * CXT) ((int*)g_fl)[i] = 0;
    if (i < 2) g_tick[i] = 0;
}

__global__ void conv_x_kern(const float* __restrict__ src) {
    int i = blockIdx.x * blockDim.x + threadIdx.x;   // over Mtot*Kd/4
    float4 v = ((const float4*)src)[i];
    __half2 p0 = __floats2half2_rn(v.x, v.y);
    __half2 p1 = __floats2half2_rn(v.z, v.w);
    const int m = i >> 7;
    const int k = (i & 127) * 4;
    const int ry = m >> 7, c = k >> 5, row = m & 127, col = k & 31;
    __half2* dst = (__half2*)&g_x0[(size_t)(ry * NCHUNK + c) * ABLK_H + row * 40 + col];
    dst[0] = p0; dst[1] = p1;
}

__global__ void conv_w_all(const float* __restrict__ w0, const float* __restrict__ w1,
                           const float* __restrict__ w2, const float* __restrict__ w3) {
    const float* srcs[4] = {w0, w1, w2, w3};
    const int mat = blockIdx.y;
    int i = blockIdx.x * blockDim.x + threadIdx.x;   // over Kd*Hn/4
    float4 v = ((const float4*)srcs[mat])[i];
    __half2 p0 = __floats2half2_rn(v.x, v.y);
    __half2 p1 = __floats2half2_rn(v.z, v.w);
    const int h = i >> 7;
    const int k = (i & 127) * 4;
    const int cx = h >> 6, c = k >> 5, row = h & 63, col = k & 31;
    __half2* dst = (__half2*)&g_w[(size_t)(((mat * CXT + cx) * NCHUNK) + c) * WBLK_H
                                  + row * 40 + col];
    dst[0] = p0; dst[1] = p1;
}

// ---------------------- fused dual GEMM + scan kernel -----------------------
#define STAGE_BYTES 20480     // A 10240 + WZ 5120 + WH 5120
#define STAGES 4
#define SMEM_BYTES (STAGES*STAGE_BYTES)   // 81920

__global__ __launch_bounds__(256, 2)
void gemm_scan(int layer, const float* __restrict__ bz, const float* __restrict__ bh,
               float* __restrict__ out, float* __restrict__ finals)
{
    extern __shared__ __align__(16) char sm[];
    const uint32_t sb = s2u(sm);
    __shared__ __align__(8) uint64_t s_full[STAGES];
    __shared__ __align__(8) uint64_t s_cons[STAGES];
    __shared__ int s_tick, s_n, s_f2;

    const int tid  = threadIdx.x;
    const int lane = tid & 31;
    const int wid  = tid >> 5;
    const int gq   = lane >> 2;
    const int tq   = lane & 3;
    const int wm   = wid & 3;
    const int wn   = wid >> 2;
    const uint32_t mbF = s2u(s_full);
    const uint32_t mbC = s2u(s_cons);

    if (tid == 0) {
        s_tick = atomicAdd(&g_tick[layer], 1);
#pragma unroll
        for (int s = 0; s < STAGES; s++) {
            mbar_init(mbF + 8 * s, 1);
            mbar_init(mbC + 8 * s, 8);   // one arrive per warp
        }
    }
    __syncthreads();
    const int tk = s_tick;
    const int ry = tk >> 3;
    const int cx = tk & 7;
    const int rowBase = ry * 128;
    const int colBase = cx * 64;
    const int batchBase = ry & ~31;

    const __half* Ab  = (layer ? g_xh : g_x0) + (size_t)ry * NCHUNK * ABLK_H;
    const __half* Wzb = g_w + (size_t)((2 * layer)     * CXT + cx) * NCHUNK * WBLK_H;
    const __half* Whb = g_w + (size_t)((2 * layer + 1) * CXT + cx) * NCHUNK * WBLK_H;

    const uint32_t aLane = (uint32_t)((32 * wm + (lane & 15)) * 80 + ((lane >> 4) << 4));
    const uint32_t bLane = (uint32_t)(((32 * wn) + ((lane >> 4) << 3) + (lane & 7)) * 80
                                      + (((lane >> 3) & 1) << 4));

    float accZ[2][4][4];
    float accH[2][4][4];
#pragma unroll
    for (int mbi = 0; mbi < 2; mbi++)
#pragma unroll
        for (int nb = 0; nb < 4; nb++)
#pragma unroll
            for (int r = 0; r < 4; r++) { accZ[mbi][nb][r] = 0.f; accH[mbi][nb][r] = 0.f; }

    // prologue: fill all 4 stages (chunks 0..3)
    if (tid == 0) {
#pragma unroll
        for (int s = 0; s < STAGES; s++) {
            const uint32_t st = sb + s * STAGE_BYTES;
            const uint32_t m  = mbF + 8 * s;
            mbar_expect(m, STAGE_BYTES);
            bulkcp(st,         Ab  + (size_t)s * ABLK_H, 10240, m);
            bulkcp(st + 10240, Wzb + (size_t)s * WBLK_H,  5120, m);
            bulkcp(st + 15360, Whb + (size_t)s * WBLK_H,  5120, m);
        }
    }

    // free-running mainloop: no CTA-wide barriers
    for (int c = 0; c < NCHUNK; c++) {
        const int st = c & 3;
        const uint32_t ph = (uint32_t)((c >> 2) & 1);
        mbar_wait(mbF + 8 * st, ph);

        const uint32_t stg = sb + st * STAGE_BYTES;
        const uint32_t aA  = stg +     0 + aLane;
        const uint32_t bZ  = stg + 10240 + bLane;
        const uint32_t bH  = stg + 15360 + bLane;

#pragma unroll
        for (int ks = 0; ks < 2; ks++) {
            const uint32_t kb = (uint32_t)(ks * 32);
            uint32_t Af[2][4], zz[2][4], hh[2][4];
#pragma unroll
            for (int mbi = 0; mbi < 2; mbi++)
                ldsm4(Af[mbi], aA + mbi * (16 * 80) + kb);
#pragma unroll
            for (int p = 0; p < 2; p++) {
                ldsm4(zz[p], bZ + p * (16 * 80) + kb);
                ldsm4(hh[p], bH + p * (16 * 80) + kb);
            }
#pragma unroll
            for (int p = 0; p < 2; p++)
#pragma unroll
                for (int q = 0; q < 2; q++)
#pragma unroll
                    for (int mbi = 0; mbi < 2; mbi++) {
                        const int nb = 2 * p + q;
                        mma_f16(accZ[mbi][nb], Af[mbi], zz[p][2*q], zz[p][2*q+1]);
                        mma_f16(accH[mbi][nb], Af[mbi], hh[p][2*q], hh[p][2*q+1]);
                    }
        }

        if (lane == 0) mbar_arrive(mbC + 8 * st);

        if (tid == 0 && c + 4 < NCHUNK) {
            // wait for all 8 warps to finish chunk c, then reload its stage
            mbar_wait(mbC + 8 * st, ph);
            const int nc = c + 4;
            const uint32_t sta = sb + st * STAGE_BYTES;
            const uint32_t m   = mbF + 8 * st;
            mbar_expect(m, STAGE_BYTES);
            bulkcp(sta,         Ab  + (size_t)nc * ABLK_H, 10240, m);
            bulkcp(sta + 10240, Wzb + (size_t)nc * WBLK_H,  5120, m);
            bulkcp(sta + 15360, Whb + (size_t)nc * WBLK_H,  5120, m);
        }
    }

    // ==================== epilogue: activation + fused scan =================
    __syncthreads();   // stage buffers dead; reuse smem

    float* aP  = (float*)sm;          // 128 x 64, stride 68
    float* bP  = aP + 8704;
    float* sA  = bP + 8704;           // 8 x 64
    float* sB  = sA + 512;
    float* hIn = sB + 512;

    // 1) activation -> planes
#pragma unroll
    for (int mbi = 0; mbi < 2; mbi++)
#pragma unroll
        for (int nb = 0; nb < 4; nb++) {
            const int col = 32 * wn + 8 * nb + 2 * tq;
            const float bz0 = bz[colBase + col], bz1 = bz[colBase + col + 1];
            const float bh0 = bh[colBase + col], bh1 = bh[colBase + col + 1];
#pragma unroll
            for (int half = 0; half < 2; half++) {
                const int row = 32 * wm + 16 * mbi + 8 * half + gq;
                const float kv0 = accZ[mbi][nb][2 * half]     + bz0;
                const float kv1 = accZ[mbi][nb][2 * half + 1] + bz1;
                const float pv0 = accH[mbi][nb][2 * half]     + bh0;
                const float pv1 = accH[mbi][nb][2 * half + 1] + bh1;
                const float a0 = 1.0f / (1.0f + __expf(kv0));
                const float a1 = 1.0f / (1.0f + __expf(kv1));
                const float z0 = 1.0f - a0;
                const float z1 = 1.0f - a1;
                const float t0 = (pv0 >= 0.f) ? (pv0 + 0.5f) : (1.0f / (1.0f + __expf(-pv0)));
                const float t1 = (pv1 >= 0.f) ? (pv1 + 0.5f) : (1.0f / (1.0f + __expf(-pv1)));
                aP[row * 68 + col    ] = a0;
                aP[row * 68 + col + 1] = a1;
                bP[row * 68 + col    ] = z0 * t0;
                bP[row * 68 + col + 1] = z1 * t1;
            }
        }
    __syncthreads();

    // 2) chunk-local compose
#pragma unroll
    for (int k = 0; k < 2; k++) {
        const int item = tid + k * 256;
        const int j = item >> 6, cc = item & 63;
        float A = 1.f, Bv = 0.f;
#pragma unroll
        for (int t = 0; t < 16; t++) {
            const int row = j * 16 + t;
            const float a = aP[row * 68 + cc];
            const float b = bP[row * 68 + cc];
            Bv = fmaf(a, Bv, b);
            A *= a;
        }
        sA[j * 64 + cc] = A;
        sB[j * 64 + cc] = Bv;
    }
    __syncthreads();

    // 3) CTA compose + publish loc
    if (tid < 64) {
        float A = 1.f, Bv = 0.f;
#pragma unroll
        for (int j = 0; j < 8; j++) {
            Bv = fmaf(sA[j * 64 + tid], Bv, sB[j * 64 + tid]);
            A *= sA[j * 64 + tid];
        }
        float2 pub; pub.x = A; pub.y = Bv;
        __stcg(&g_loc[layer][(size_t)ry * Hn + colBase + tid], pub);
        __threadfence();
    }
    __syncthreads();
    if (tid == 0) atomicExch(&g_fl[layer][ry * 8 + cx], 1);

    // 4) lookback
    float hstart = 0.5f;
    if (ry != batchBase) {
        float alpha = 1.f, beta = 0.f;
        int p = ry - 1;
        for (;;) {
            if (tid < 32) {
                int rel = p - lane;
                int f = 0;
                if (rel >= batchBase) f = atomicAdd(&g_fl[layer][rel * 8 + cx], 0);
                unsigned m0 = __ballot_sync(0xffffffffu, f == 0);
                unsigned m2 = __ballot_sync(0xffffffffu, f == 2);
                int n = m0 ? (__ffs(m0) - 1) : 32;
                unsigned lim = (n >= 32) ? 0xffffffffu : ((1u << n) - 1u);
                unsigned m2v = m2 & lim;
                int f2 = m2v ? (__ffs(m2v) - 1) : -1;
                if (lane == 0) { s_n = n; s_f2 = f2; }
            }
            __syncthreads();
            const int n = s_n, f2 = s_f2;
            __syncthreads();

            if (f2 >= 0) {
                if (tid < 64) {
                    for (int l = 0; l < f2; l++) {
                        float2 pv = __ldcg(&g_loc[layer][(size_t)(p - l) * Hn + colBase + tid]);
                        beta  = fmaf(alpha, pv.y, beta);
                        alpha *= pv.x;
                    }
                    float iv = __ldcg(&g_inc[layer][(size_t)(p - f2) * Hn + colBase + tid]);
                    hstart = fmaf(alpha, iv, beta);
                }
                break;
            }
            if (tid < 64) {
                for (int l = 0; l < n; l++) {
                    float2 pv = __ldcg(&g_loc[layer][(size_t)(p - l) * Hn + colBase + tid]);
                    beta  = fmaf(alpha, pv.y, beta);
                    alpha *= pv.x;
                }
            }
            p -= n;
            if (p < batchBase) {
                if (tid < 64) hstart = fmaf(alpha, 0.5f, beta);
                break;
            }
        }
    }

    // 5) chunk entry states + publish inclusive
    if (tid < 64) {
        float h = hstart;
#pragma unroll
        for (int j = 0; j < 8; j++) {
            hIn[j * 64 + tid] = h;
            h = fmaf(sA[j * 64 + tid], h, sB[j * 64 + tid]);
        }
        __stcg(&g_inc[layer][(size_t)ry * Hn + colBase + tid], h);
        __threadfence();
        if ((ry & 31) == 31)
            finals[(ry >> 5) * Hn + colBase + tid] = h;
    }
    __syncthreads();
    if (tid == 0) atomicExch(&g_fl[layer][ry * 8 + cx], 2);

    // 6) emit hidden states
#pragma unroll
    for (int k = 0; k < 2; k++) {
        const int item = tid + k * 256;
        const int j = item >> 6, cc = item & 63;
        float h = hIn[j * 64 + cc];
        if (layer == 0) {
            __half* dst = g_xh + (size_t)(ry * NCHUNK + 2 * cx + (cc >> 5)) * ABLK_H
                          + (cc & 31);
#pragma unroll
            for (int t = 0; t < 16; t++) {
                const int row = j * 16 + t;
                h = fmaf(aP[row * 68 + cc], h, bP[row * 68 + cc]);
                dst[row * 40] = __float2half(h);
            }
        } else {
#pragma unroll
            for (int t = 0; t < 16; t++) {
                const int row = j * 16 + t;
                h = fmaf(aP[row * 68 + cc], h, bP[row * 68 + cc]);
                __stcs(&out[(size_t)(rowBase + row) * Hn + colBase + cc], h);
            }
        }
    }
}

// --------------------------------- launch ----------------------------------
extern "C" void kernel_launch(void* const* d_in, const int* in_sizes, int n_in,
                              void* d_out, int out_size)
{
    const float* x   = (const float*)d_in[0];
    const float* wz0 = (const float*)d_in[1];
    const float* bz0 = (const float*)d_in[2];
    const float* wh0 = (const float*)d_in[3];
    const float* bh0 = (const float*)d_in[4];
    const float* wz1 = (const float*)d_in[5];
    const float* bz1 = (const float*)d_in[6];
    const float* wh1 = (const float*)d_in[7];
    const float* bh1 = (const float*)d_in[8];

    float* out    = (float*)d_out;
    float* finals = out + (size_t)Mtot * Hn;

    static int smem_set = 0;
    if (!smem_set) {
        cudaFuncSetAttribute(gemm_scan, cudaFuncAttributeMaxDynamicSharedMemorySize,
                             SMEM_BYTES);
        smem_set = 1;
    }

    clear_state<<<(2 * RYT * CXT + 255) / 256, 256>>>();
    conv_x_kern<<<(Mtot * Kd / 4) / 256, 256>>>(x);
    conv_w_all<<<dim3((Kd * Hn / 4) / 256, 4), 256>>>(wz0, wh0, wz1, wh1);

    gemm_scan<<<RYT * CXT, 256, SMEM_BYTES>>>(0, bz0, bh0, nullptr, finals);
    gemm_scan<<<RYT * CXT, 256, SMEM_BYTES>>>(1, bz1, bh1, out, finals + Bb * Hn);
}

// round 13
// speedup vs baseline: 1.5745x; 1.0877x over previous
#include <cuda_runtime.h>
#include <cuda_fp16.h>
#include <math.h>
#include <stdint.h>

#define Bb 8
#define Ss 4096
#define Hn 512
#define Kd 512
#define Mtot (Bb*Ss)          // 32768
#define RYT 256               // row tiles (128 rows)
#define CXT 8                 // col tiles (64 cols)
#define NCHUNK 16             // K chunks of 32

// Tiled gmem images matching smem layout: 80B (40-half) padded rows.
#define ABLK_H 5120
#define WBLK_H 2560

__device__ __align__(256) __half  g_x0[(size_t)RYT*NCHUNK*ABLK_H];
__device__ __align__(256) __half  g_xh[(size_t)RYT*NCHUNK*ABLK_H];
__device__ __align__(256) __half  g_w [(size_t)4*CXT*NCHUNK*WBLK_H];
__device__ __align__(256) float2  g_loc[2][RYT*Hn];
__device__ __align__(256) float   g_inc[2][RYT*Hn];
__device__ __align__(256) int     g_fl [2][RYT*CXT];
__device__ __align__(256) int     g_rdy[RYT];
__device__ int g_tick;

// ------------------------------ helpers ------------------------------------
__device__ __forceinline__ uint32_t s2u(const void* p) {
    uint32_t a;
    asm("{ .reg .u64 t; cvta.to.shared.u64 t, %1; cvt.u32.u64 %0, t; }"
        : "=r"(a) : "l"(p));
    return a;
}

__device__ __forceinline__ void mma_f16(float* d, const uint32_t* a,
                                        uint32_t b0, uint32_t b1) {
    asm volatile(
        "mma.sync.aligned.m16n8k16.row.col.f32.f16.f16.f32 "
        "{%0,%1,%2,%3}, {%4,%5,%6,%7}, {%8,%9}, {%0,%1,%2,%3};"
        : "+f"(d[0]), "+f"(d[1]), "+f"(d[2]), "+f"(d[3])
        : "r"(a[0]), "r"(a[1]), "r"(a[2]), "r"(a[3]), "r"(b0), "r"(b1));
}

__device__ __forceinline__ void ldsm4(uint32_t* r, uint32_t addr) {
    asm volatile("ldmatrix.sync.aligned.m8n8.x4.shared.b16 {%0,%1,%2,%3}, [%4];"
        : "=r"(r[0]), "=r"(r[1]), "=r"(r[2]), "=r"(r[3]) : "r"(addr));
}

__device__ __forceinline__ void mbar_init(uint32_t m, uint32_t cnt) {
    asm volatile("mbarrier.init.shared.b64 [%0], %1;" :: "r"(m), "r"(cnt) : "memory");
}
__device__ __forceinline__ void mbar_expect(uint32_t m, uint32_t bytes) {
    asm volatile("mbarrier.arrive.expect_tx.shared.b64 _, [%0], %1;"
                 :: "r"(m), "r"(bytes) : "memory");
}
__device__ __forceinline__ void mbar_arrive(uint32_t m) {
    asm volatile("mbarrier.arrive.shared.b64 _, [%0];" :: "r"(m) : "memory");
}
__device__ __forceinline__ void mbar_wait(uint32_t m, uint32_t parity) {
    asm volatile(
        "{\n\t.reg .pred P1;\n\t"
        "WL%=:\n\t"
        "mbarrier.try_wait.parity.acquire.cta.shared::cta.b64 P1, [%0], %1, 0x989680;\n\t"
        "@P1 bra.uni WD%=;\n\t"
        "bra.uni WL%=;\n\t"
        "WD%=:\n\t}"
        :: "r"(m), "r"(parity) : "memory");
}
__device__ __forceinline__ void bulkcp(uint32_t dst, const void* gsrc,
                                       uint32_t bytes, uint32_t mbar) {
    uint64_t ga;
    asm volatile("cvta.to.global.u64 %0, %1;" : "=l"(ga) : "l"(gsrc));
    asm volatile(
        "cp.async.bulk.shared::cluster.global.mbarrier::complete_tx::bytes "
        "[%0], [%1], %2, [%3];"
        :: "r"(dst), "l"(ga), "r"(bytes), "r"(mbar) : "memory");
}

// batched affine compose over predecessors pTop, pTop-1, ..., pTop-cnt+1
__device__ __forceinline__ void compose_n(int layer, int pTop, int cnt, int col,
                                          float& alpha, float& beta) {
    int l = 0;
    while (l + 8 <= cnt) {
        float2 buf[8];
#pragma unroll
        for (int j = 0; j < 8; j++)
            buf[j] = __ldcg(&g_loc[layer][(size_t)(pTop - l - j) * Hn + col]);
#pragma unroll
        for (int j = 0; j < 8; j++) {
            beta  = fmaf(alpha, buf[j].y, beta);
            alpha *= buf[j].x;
        }
        l += 8;
    }
    for (; l < cnt; l++) {
        float2 pv = __ldcg(&g_loc[layer][(size_t)(pTop - l) * Hn + col]);
        beta  = fmaf(alpha, pv.y, beta);
        alpha *= pv.x;
    }
}

// ------------------------------- setup kernels -----------------------------
__global__ void clear_state()
{
    int i = blockIdx.x * blockDim.x + threadIdx.x;
    if (i < 2 * RYT * CXT) ((int*)g_fl)[i] = 0;
    if (i < RYT) g_rdy[i] = 0;
    if (i == 0) g_tick = 0;
}

__global__ void conv_x_kern(const float* __restrict__ src) {
    int i = blockIdx.x * blockDim.x + threadIdx.x;   // over Mtot*Kd/4
    float4 v = ((const float4*)src)[i];
    __half2 p0 = __floats2half2_rn(v.x, v.y);
    __half2 p1 = __floats2half2_rn(v.z, v.w);
    const int m = i >> 7;
    const int k = (i & 127) * 4;
    const int ry = m >> 7, c = k >> 5, row = m & 127, col = k & 31;
    __half2* dst = (__half2*)&g_x0[(size_t)(ry * NCHUNK + c) * ABLK_H + row * 40 + col];
    dst[0] = p0; dst[1] = p1;
}

__global__ void conv_w_all(const float* __restrict__ w0, const float* __restrict__ w1,
                           const float* __restrict__ w2, const float* __restrict__ w3) {
    const float* srcs[4] = {w0, w1, w2, w3};
    const int mat = blockIdx.y;
    int i = blockIdx.x * blockDim.x + threadIdx.x;   // over Kd*Hn/4
    float4 v = ((const float4*)srcs[mat])[i];
    __half2 p0 = __floats2half2_rn(v.x, v.y);
    __half2 p1 = __floats2half2_rn(v.z, v.w);
    const int h = i >> 7;
    const int k = (i & 127) * 4;
    const int cx = h >> 6, c = k >> 5, row = h & 63, col = k & 31;
    __half2* dst = (__half2*)&g_w[(size_t)(((mat * CXT + cx) * NCHUNK) + c) * WBLK_H
                                  + row * 40 + col];
    dst[0] = p0; dst[1] = p1;
}

// ---------------- fused dual GEMM + scan, BOTH layers in one kernel ---------
#define STAGE_BYTES 20480     // A 10240 + WZ 5120 + WH 5120
#define STAGES 4
#define SMEM_BYTES (STAGES*STAGE_BYTES)   // 81920

__global__ __launch_bounds__(256, 2)
void gemm_scan(const float* __restrict__ bz0, const float* __restrict__ bh0,
               const float* __restrict__ bz1, const float* __restrict__ bh1,
               float* __restrict__ out, float* __restrict__ finalsBase)
{
    extern __shared__ __align__(16) char sm[];
    const uint32_t sb = s2u(sm);
    __shared__ __align__(8) uint64_t s_full[STAGES];
    __shared__ __align__(8) uint64_t s_cons[STAGES];
    __shared__ int s_tick, s_n, s_f2;

    const int tid  = threadIdx.x;
    const int lane = tid & 31;
    const int wid  = tid >> 5;
    const int gq   = lane >> 2;
    const int tq   = lane & 3;
    const int wm   = wid & 3;
    const int wn   = wid >> 2;
    const uint32_t mbF = s2u(s_full);
    const uint32_t mbC = s2u(s_cons);

    if (tid == 0) {
        s_tick = atomicAdd(&g_tick, 1);
#pragma unroll
        for (int s = 0; s < STAGES; s++) {
            mbar_init(mbF + 8 * s, 1);
            mbar_init(mbC + 8 * s, 8);
        }
    }
    __syncthreads();
    const int tk    = s_tick;
    const int layer = (tk >= RYT * CXT) ? 1 : 0;
    const int tk2   = tk & (RYT * CXT - 1);
    const int ry = tk2 >> 3;
    const int cx = tk2 & 7;
    const int rowBase = ry * 128;
    const int colBase = cx * 64;
    const int batchBase = ry & ~31;

    const float* bz = layer ? bz1 : bz0;
    const float* bh = layer ? bh1 : bh0;
    float* finals = finalsBase + layer * Bb * Hn;

    // layer-1 CTA: wait until all 8 layer-0 CTAs of this row tile published g_xh
    if (layer == 1) {
        if (tid == 0) {
            while (atomicAdd(&g_rdy[ry], 0) < 8) __nanosleep(64);
        }
        __syncthreads();
        __threadfence();
    }

    const __half* Ab  = (layer ? g_xh : g_x0) + (size_t)ry * NCHUNK * ABLK_H;
    const __half* Wzb = g_w + (size_t)((2 * layer)     * CXT + cx) * NCHUNK * WBLK_H;
    const __half* Whb = g_w + (size_t)((2 * layer + 1) * CXT + cx) * NCHUNK * WBLK_H;

    const uint32_t aLane = (uint32_t)((32 * wm + (lane & 15)) * 80 + ((lane >> 4) << 4));
    const uint32_t bLane = (uint32_t)(((32 * wn) + ((lane >> 4) << 3) + (lane & 7)) * 80
                                      + (((lane >> 3) & 1) << 4));

    float accZ[2][4][4];
    float accH[2][4][4];
#pragma unroll
    for (int mbi = 0; mbi < 2; mbi++)
#pragma unroll
        for (int nb = 0; nb < 4; nb++)
#pragma unroll
            for (int r = 0; r < 4; r++) { accZ[mbi][nb][r] = 0.f; accH[mbi][nb][r] = 0.f; }

    // prologue: fill all 4 stages (chunks 0..3)
    if (tid == 0) {
#pragma unroll
        for (int s = 0; s < STAGES; s++) {
            const uint32_t st = sb + s * STAGE_BYTES;
            const uint32_t m  = mbF + 8 * s;
            mbar_expect(m, STAGE_BYTES);
            bulkcp(st,         Ab  + (size_t)s * ABLK_H, 10240, m);
            bulkcp(st + 10240, Wzb + (size_t)s * WBLK_H,  5120, m);
            bulkcp(st + 15360, Whb + (size_t)s * WBLK_H,  5120, m);
        }
    }

    // mainloop: unrolled so stage offsets are immediates
    for (int cg = 0; cg < 4; cg++) {
        const uint32_t ph = (uint32_t)(cg & 1);
#pragma unroll
        for (int s = 0; s < 4; s++) {
            const int c = cg * 4 + s;
            mbar_wait(mbF + 8 * s, ph);

            const uint32_t stg = sb + s * STAGE_BYTES;
            const uint32_t aA  = stg +     0 + aLane;
            const uint32_t bZ  = stg + 10240 + bLane;
            const uint32_t bH  = stg + 15360 + bLane;

#pragma unroll
            for (int ks = 0; ks < 2; ks++) {
                const uint32_t kb = (uint32_t)(ks * 32);
                uint32_t Af[2][4], zz[2][4], hh[2][4];
#pragma unroll
                for (int mbi = 0; mbi < 2; mbi++)
                    ldsm4(Af[mbi], aA + mbi * (16 * 80) + kb);
#pragma unroll
                for (int p = 0; p < 2; p++) {
                    ldsm4(zz[p], bZ + p * (16 * 80) + kb);
                    ldsm4(hh[p], bH + p * (16 * 80) + kb);
                }
#pragma unroll
                for (int p = 0; p < 2; p++)
#pragma unroll
                    for (int q = 0; q < 2; q++)
#pragma unroll
                        for (int mbi = 0; mbi < 2; mbi++) {
                            const int nb = 2 * p + q;
                            mma_f16(accZ[mbi][nb], Af[mbi], zz[p][2*q], zz[p][2*q+1]);
                            mma_f16(accH[mbi][nb], Af[mbi], hh[p][2*q], hh[p][2*q+1]);
                        }
            }

            if (lane == 0) mbar_arrive(mbC + 8 * s);

            if (tid == 0 && c + 4 < NCHUNK) {
                mbar_wait(mbC + 8 * s, ph);
                const int nc = c + 4;
                const uint32_t sta = sb + s * STAGE_BYTES;
                const uint32_t m   = mbF + 8 * s;
                mbar_expect(m, STAGE_BYTES);
                bulkcp(sta,         Ab  + (size_t)nc * ABLK_H, 10240, m);
                bulkcp(sta + 10240, Wzb + (size_t)nc * WBLK_H,  5120, m);
                bulkcp(sta + 15360, Whb + (size_t)nc * WBLK_H,  5120, m);
            }
        }
    }

    // ==================== epilogue: activation + fused scan =================
    __syncthreads();

    float* aP  = (float*)sm;          // 128 x 64, stride 68
    float* bP  = aP + 8704;
    float* sA  = bP + 8704;           // 8 x 64
    float* sB  = sA + 512;
    float* hIn = sB + 512;

#pragma unroll
    for (int mbi = 0; mbi < 2; mbi++)
#pragma unroll
        for (int nb = 0; nb < 4; nb++) {
            const int col = 32 * wn + 8 * nb + 2 * tq;
            const float bzv0 = bz[colBase + col], bzv1 = bz[colBase + col + 1];
            const float bhv0 = bh[colBase + col], bhv1 = bh[colBase + col + 1];
#pragma unroll
            for (int half = 0; half < 2; half++) {
                const int row = 32 * wm + 16 * mbi + 8 * half + gq;
                const float kv0 = accZ[mbi][nb][2 * half]     + bzv0;
                const float kv1 = accZ[mbi][nb][2 * half + 1] + bzv1;
                const float pv0 = accH[mbi][nb][2 * half]     + bhv0;
                const float pv1 = accH[mbi][nb][2 * half + 1] + bhv1;
                const float a0 = 1.0f / (1.0f + __expf(kv0));
                const float a1 = 1.0f / (1.0f + __expf(kv1));
                const float z0 = 1.0f - a0;
                const float z1 = 1.0f - a1;
                const float t0 = (pv0 >= 0.f) ? (pv0 + 0.5f) : (1.0f / (1.0f + __expf(-pv0)));
                const float t1 = (pv1 >= 0.f) ? (pv1 + 0.5f) : (1.0f / (1.0f + __expf(-pv1)));
                aP[row * 68 + col    ] = a0;
                aP[row * 68 + col + 1] = a1;
                bP[row * 68 + col    ] = z0 * t0;
                bP[row * 68 + col + 1] = z1 * t1;
            }
        }
    __syncthreads();

    // chunk-local compose
#pragma unroll
    for (int k = 0; k < 2; k++) {
        const int item = tid + k * 256;
        const int j = item >> 6, cc = item & 63;
        float A = 1.f, Bv = 0.f;
#pragma unroll
        for (int t = 0; t < 16; t++) {
            const int row = j * 16 + t;
            const float a = aP[row * 68 + cc];
            const float b = bP[row * 68 + cc];
            Bv = fmaf(a, Bv, b);
            A *= a;
        }
        sA[j * 64 + cc] = A;
        sB[j * 64 + cc] = Bv;
    }
    __syncthreads();

    // CTA compose + publish loc
    if (tid < 64) {
        float A = 1.f, Bv = 0.f;
#pragma unroll
        for (int j = 0; j < 8; j++) {
            Bv = fmaf(sA[j * 64 + tid], Bv, sB[j * 64 + tid]);
            A *= sA[j * 64 + tid];
        }
        float2 pub; pub.x = A; pub.y = Bv;
        __stcg(&g_loc[layer][(size_t)ry * Hn + colBase + tid], pub);
        __threadfence();
    }
    __syncthreads();
    if (tid == 0) atomicExch(&g_fl[layer][ry * 8 + cx], 1);

    // lookback (batched compose)
    float hstart = 0.5f;
    if (ry != batchBase) {
        float alpha = 1.f, beta = 0.f;
        int p = ry - 1;
        for (;;) {
            if (tid < 32) {
                int rel = p - lane;
                int f = 0;
                if (rel >= batchBase) f = atomicAdd(&g_fl[layer][rel * 8 + cx], 0);
                unsigned m0 = __ballot_sync(0xffffffffu, f == 0);
                unsigned m2 = __ballot_sync(0xffffffffu, f == 2);
                int n = m0 ? (__ffs(m0) - 1) : 32;
                unsigned lim = (n >= 32) ? 0xffffffffu : ((1u << n) - 1u);
                unsigned m2v = m2 & lim;
                int f2 = m2v ? (__ffs(m2v) - 1) : -1;
                if (lane == 0) { s_n = n; s_f2 = f2; }
            }
            __syncthreads();
            const int n = s_n, f2 = s_f2;
            __syncthreads();

            if (f2 >= 0) {
                if (tid < 64) {
                    compose_n(layer, p, f2, colBase + tid, alpha, beta);
                    float iv = __ldcg(&g_inc[layer][(size_t)(p - f2) * Hn + colBase + tid]);
                    hstart = fmaf(alpha, iv, beta);
                }
                break;
            }
            if (tid < 64)
                compose_n(layer, p, n, colBase + tid, alpha, beta);
            p -= n;
            if (p < batchBase) {
                if (tid < 64) hstart = fmaf(alpha, 0.5f, beta);
                break;
            }
        }
    }

    // chunk entry states + publish inclusive
    if (tid < 64) {
        float h = hstart;
#pragma unroll
        for (int j = 0; j < 8; j++) {
            hIn[j * 64 + tid] = h;
            h = fmaf(sA[j * 64 + tid], h, sB[j * 64 + tid]);
        }
        __stcg(&g_inc[layer][(size_t)ry * Hn + colBase + tid], h);
        __threadfence();
        if ((ry & 31) == 31)
            finals[(ry >> 5) * Hn + colBase + tid] = h;
    }
    __syncthreads();
    if (tid == 0) atomicExch(&g_fl[layer][ry * 8 + cx], 2);

    // emit hidden states
#pragma unroll
    for (int k = 0; k < 2; k++) {
        const int item = tid + k * 256;
        const int j = item >> 6, cc = item & 63;
        float h = hIn[j * 64 + cc];
        if (layer == 0) {
            __half* dst = g_xh + (size_t)(ry * NCHUNK + 2 * cx + (cc >> 5)) * ABLK_H
                          + (cc & 31);
#pragma unroll
            for (int t = 0; t < 16; t++) {
                const int row = j * 16 + t;
                h = fmaf(aP[row * 68 + cc], h, bP[row * 68 + cc]);
                dst[row * 40] = __float2half(h);
            }
        } else {
#pragma unroll
            for (int t = 0; t < 16; t++) {
                const int row = j * 16 + t;
                h = fmaf(aP[row * 68 + cc], h, bP[row * 68 + cc]);
                __stcs(&out[(size_t)(rowBase + row) * Hn + colBase + cc], h);
            }
        }
    }

    // layer-0: signal this row tile's hidden block is ready for layer 1
    if (layer == 0) {
        __syncthreads();
        if (tid == 0) {
            __threadfence();
            atomicAdd(&g_rdy[ry], 1);
        }
    }
}

// --------------------------------- launch ----------------------------------
extern "C" void kernel_launch(void* const* d_in, const int* in_sizes, int n_in,
                              void* d_out, int out_size)
{
    const float* x   = (const float*)d_in[0];
    const float* wz0 = (const float*)d_in[1];
    const float* bz0 = (const float*)d_in[2];
    const float* wh0 = (const float*)d_in[3];
    const float* bh0 = (const float*)d_in[4];
    const float* wz1 = (const float*)d_in[5];
    const float* bz1 = (const float*)d_in[6];
    const float* wh1 = (const float*)d_in[7];
    const float* bh1 = (const float*)d_in[8];

    float* out    = (float*)d_out;
    float* finals = out + (size_t)Mtot * Hn;

    static int smem_set = 0;
    if (!smem_set) {
        cudaFuncSetAttribute(gemm_scan, cudaFuncAttributeMaxDynamicSharedMemorySize,
                             SMEM_BYTES);
        smem_set = 1;
    }

    clear_state<<<(2 * RYT * CXT + 255) / 256, 256>>>();
    conv_x_kern<<<(Mtot * Kd / 4) / 256, 256>>>(x);
    conv_w_all<<<dim3((Kd * Hn / 4) / 256, 4), 256>>>(wz0, wh0, wz1, wh1);

    gemm_scan<<<2 * RYT * CXT, 256, SMEM_BYTES>>>(bz0, bh0, bz1, bh1, out, finals);
}